// round 8
// baseline (speedup 1.0000x reference)
#include <cuda_runtime.h>
#include <cstdint>

#define U_ 128
#define C_ 64
#define B_ 16
#define T_ 128
#define RANKS 8          // CTAs per cluster (one cluster per batch)
#define JPC 16           // post-neurons owned per CTA
#define IPL 8            // pre-neurons per lane (128 / 16)
#define CPL 4            // sensory channels per lane (64 / 16)
#define NTH 256
#define UNFOLDS 6
#define EPS_ 1e-8f
#define NB 4             // v-set ring buffers
#define SENT 0x7FC00BADu // NaN-payload sentinel (unreachable by arithmetic here)

// ---------------- device scratch (no allocations allowed) ----------------
__device__ float g_rsK[U_*U_];   //  sigma * 0.5
__device__ float g_rcK[U_*U_];   // -sigma * mu * 0.5
__device__ float g_rwE[U_*U_];   //  softplus(w) * erev * 0.5
__device__ float g_ssK[C_*U_];   //  ssigma * iw * 0.5
__device__ float g_scK[C_*U_];   //  ssigma * (ib - smu) * 0.5
__device__ float g_swE[C_*U_];   //  softplus(sw) * serev * 0.5
__device__ float g_cmt[U_];      //  softplus(cm) * 6
__device__ float g_AA[U_];       //  cmt + softplus(gleak)
__device__ float g_CC[U_];       //  softplus(gleak) * vleak

__device__ __forceinline__ float softplus_f(float x) {
    return fmaxf(x, 0.0f) + log1pf(expf(-fabsf(x)));
}

__global__ void ltc_prep(const float* __restrict__ sigma, const float* __restrict__ mu,
                         const float* __restrict__ w,     const float* __restrict__ erev,
                         const float* __restrict__ ssig,  const float* __restrict__ smu,
                         const float* __restrict__ sw,    const float* __restrict__ serev,
                         const float* __restrict__ iw,    const float* __restrict__ ib,
                         const float* __restrict__ gleak, const float* __restrict__ vleak,
                         const float* __restrict__ cm)
{
    int idx = blockIdx.x * blockDim.x + threadIdx.x;
    if (idx < U_*U_) {
        float sg = sigma[idx];
        g_rsK[idx] =  sg * 0.5f;
        g_rcK[idx] = -sg * mu[idx] * 0.5f;
        g_rwE[idx] =  softplus_f(w[idx]) * erev[idx] * 0.5f;
    }
    if (idx < C_*U_) {
        int c = idx / U_;
        float sg = ssig[idx];
        g_ssK[idx] = sg * iw[c] * 0.5f;
        g_scK[idx] = sg * (ib[c] - smu[idx]) * 0.5f;
        g_swE[idx] = softplus_f(sw[idx]) * serev[idx] * 0.5f;
    }
    if (idx < U_) {
        float gl  = softplus_f(gleak[idx]);
        float cmt = softplus_f(cm[idx]) * (float)UNFOLDS;
        g_cmt[idx] = cmt;
        g_AA[idx]  = cmt + gl;
        g_CC[idx]  = gl * vleak[idx];
    }
}

// ---------------- PTX helpers ----------------
__device__ __forceinline__ uint32_t smem_u32(const void* p) {
    uint32_t a;
    asm("{ .reg .u64 t; cvta.to.shared.u64 t, %1; cvt.u32.u64 %0, t; }" : "=r"(a) : "l"(p));
    return a;
}
__device__ __forceinline__ uint32_t mapa_u32(uint32_t a, uint32_t r) {
    uint32_t o;
    asm("mapa.shared::cluster.u32 %0, %1, %2;" : "=r"(o) : "r"(a), "r"(r));
    return o;
}
__device__ __forceinline__ void cluster_sync_() {
    asm volatile("barrier.cluster.arrive.aligned;" ::: "memory");
    asm volatile("barrier.cluster.wait.aligned;"   ::: "memory");
}
__device__ __forceinline__ float tanhf_a(float x) { float y; asm("tanh.approx.f32 %0, %1;" : "=f"(y) : "f"(x)); return y; }
__device__ __forceinline__ float rcpf_(float x)   { float y; asm("rcp.approx.f32 %0, %1;"  : "=f"(y) : "f"(x)); return y; }

// plain remote SMEM store (fire-and-forget; visibility detected by polling)
__device__ __forceinline__ void st_cluster_f32(uint32_t addr, float v) {
    asm volatile("st.shared::cluster.b32 [%0], %1;"
                 :: "r"(addr), "r"(__float_as_uint(v)) : "memory");
}
__device__ __forceinline__ void ld_vol_v4(uint32_t addr, uint32_t& a, uint32_t& b, uint32_t& c, uint32_t& d) {
    asm volatile("ld.volatile.shared.v4.b32 {%0,%1,%2,%3}, [%4];"
                 : "=r"(a), "=r"(b), "=r"(c), "=r"(d) : "r"(addr));
}
__device__ __forceinline__ uint32_t ld_vol_b32(uint32_t addr) {
    uint32_t v;
    asm volatile("ld.volatile.shared.b32 %0, [%1];" : "=r"(v) : "r"(addr));
    return v;
}

// ---------------- main kernel: one cluster (8 CTAs) per batch ----------------
// CTA `rank` owns post-neurons j in [rank*16, rank*16+16). 16 lanes per j,
// 8 pre-neurons per lane. Finished v's cross the cluster as plain remote
// stores into a 4-deep sentinel-tagged ring; receivers poll only their words.
__global__ void __cluster_dims__(RANKS, 1, 1) __launch_bounds__(NTH, 1)
ltc_main(const float* __restrict__ x, const float* __restrict__ h0,
         const float* __restrict__ ow, const float* __restrict__ ob,
         float* __restrict__ out)
{
    __shared__ __align__(16) float sV[NB][U_];  // ring of v-sets (set k -> buffer k&3)
    __shared__ float sX[T_][C_];                // full input slice for this batch (32 KB)

    const int tid  = threadIdx.x;
    const int b    = blockIdx.x / RANKS;
    const int rank = blockIdx.x % RANKS;
    const int jj   = tid >> 4;         // local post-neuron (0..15)
    const int s    = tid & 15;         // lane within j-group (0..15)
    const int jg   = rank * JPC + jj;  // global post-neuron

    // ---- weights into registers (live across entire run) ----
    float rs[IPL], rc[IPL], rw[IPL];
    #pragma unroll
    for (int k = 0; k < IPL; k++) {
        int idx = (s * IPL + k) * U_ + jg;
        rs[k] = g_rsK[idx]; rc[k] = g_rcK[idx]; rw[k] = g_rwE[idx];
    }
    float ssk[CPL], sck[CPL], swe[CPL];
    #pragma unroll
    for (int k = 0; k < CPL; k++) {
        int idx = (s * CPL + k) * U_ + jg;
        ssk[k] = g_ssK[idx]; sck[k] = g_scK[idx]; swe[k] = g_swE[idx];
    }
    const float pcm = g_cmt[jg], pa = g_AA[jg], pcc = g_CC[jg];
    const float pow_ = ow[jg], pob_ = ob[jg];

    // stage x[b] into SMEM (float4)
    {
        const float4* xg = (const float4*)(x + (size_t)b * T_ * C_);
        float4* xs = (float4*)&sX[0][0];
        #pragma unroll 4
        for (int i = tid; i < T_ * C_ / 4; i += NTH) xs[i] = xg[i];
    }
    // buffer 0 = h0 (real values pass the poll immediately); buffers 1..3 = sentinel
    if (tid < U_) {
        sV[0][tid] = h0[b * U_ + tid];
        ((volatile uint32_t*)&sV[1][0])[tid] = SENT;
        ((volatile uint32_t*)&sV[2][0])[tid] = SENT;
        ((volatile uint32_t*)&sV[3][0])[tid] = SENT;
    }
    __syncthreads();
    cluster_sync_();                   // all buffers initialized before any remote store

    const uint32_t svb = smem_u32(&sV[0][0]);
    // remote base: lanes 0..7 of each group deliver the group's v to rank s
    const uint32_t rbase = mapa_u32(svb, (uint32_t)(s & 7)) + (uint32_t)jg * 4u;
    const bool sender = (s < 8);

    float vlast = 0.f;

    for (int t = 0; t < T_; t++) {
        // ---- sensory partials (local; overlapped with prior send's transit) ----
        float xn = 0.f, xd = 0.f;
        #pragma unroll
        for (int k = 0; k < CPL; k++) {
            float xv = sX[t][s * CPL + k];
            float tt = tanhf_a(fmaf(ssk[k], xv, sck[k]));
            float p  = fmaf(swe[k], tt, swe[k]);   // w_pos*erev*sigmoid
            xn += p; xd += fabsf(p);
        }

        const int kb = (2 * t) & 3;    // (6t) & 3
        #pragma unroll
        for (int u = 0; u < UNFOLDS; u++) {
            const int m  = (kb + u) & 3;        // buffer holding v-set 6t+u
            const int mw = (kb + u + 1) & 3;    // buffer receiving v-set 6t+u+1
            const int mr = (kb + u + 2) & 3;    // buffer to re-sentinel (set 6t+u-2)

            // ---- poll exactly the 9 words this thread consumes ----
            const uint32_t abase = svb + (uint32_t)m * (U_ * 4) + (uint32_t)(s * IPL) * 4;
            const uint32_t avv   = svb + (uint32_t)m * (U_ * 4) + (uint32_t)jg * 4;
            uint32_t w0,w1,w2,w3,w4,w5,w6,w7,w8;
            while (true) {
                ld_vol_v4(abase,      w0, w1, w2, w3);
                ld_vol_v4(abase + 16, w4, w5, w6, w7);
                w8 = ld_vol_b32(avv);
                if ((w0 != SENT) & (w1 != SENT) & (w2 != SENT) & (w3 != SENT) &
                    (w4 != SENT) & (w5 != SENT) & (w6 != SENT) & (w7 != SENT) &
                    (w8 != SENT)) break;
            }
            // re-sentinel the 2-rounds-stale buffer (safe: see lifecycle proof)
            if (tid < U_)
                ((volatile uint32_t*)&sV[mr][0])[tid] = SENT;

            // recurrent partial over my 8 pre-neurons (sensory folded in)
            const float vi0 = __uint_as_float(w0), vi1 = __uint_as_float(w1);
            const float vi2 = __uint_as_float(w2), vi3 = __uint_as_float(w3);
            const float vi4 = __uint_as_float(w4), vi5 = __uint_as_float(w5);
            const float vi6 = __uint_as_float(w6), vi7 = __uint_as_float(w7);
            float t0 = tanhf_a(fmaf(rs[0], vi0, rc[0]));
            float t1 = tanhf_a(fmaf(rs[1], vi1, rc[1]));
            float t2 = tanhf_a(fmaf(rs[2], vi2, rc[2]));
            float t3 = tanhf_a(fmaf(rs[3], vi3, rc[3]));
            float t4 = tanhf_a(fmaf(rs[4], vi4, rc[4]));
            float t5 = tanhf_a(fmaf(rs[5], vi5, rc[5]));
            float t6 = tanhf_a(fmaf(rs[6], vi6, rc[6]));
            float t7 = tanhf_a(fmaf(rs[7], vi7, rc[7]));
            float p0 = fmaf(rw[0], t0, rw[0]), p1 = fmaf(rw[1], t1, rw[1]);
            float p2 = fmaf(rw[2], t2, rw[2]), p3 = fmaf(rw[3], t3, rw[3]);
            float p4 = fmaf(rw[4], t4, rw[4]), p5 = fmaf(rw[5], t5, rw[5]);
            float p6 = fmaf(rw[6], t6, rw[6]), p7 = fmaf(rw[7], t7, rw[7]);
            float rnA = (xn + p0) + p1, rnB = (p2 + p3), rnC = (p4 + p5), rnD = (p6 + p7);
            float rdA = (xd + fabsf(p0)) + fabsf(p1), rdB = fabsf(p2) + fabsf(p3);
            float rdC = fabsf(p4) + fabsf(p5),        rdD = fabsf(p6) + fabsf(p7);
            float rn = (rnA + rnB) + (rnC + rnD);
            float rd = (rdA + rdB) + (rdC + rdD);
            // butterfly over the 16-lane group (all lanes end with full sums)
            #pragma unroll
            for (int d = 8; d >= 1; d >>= 1) {
                rn += __shfl_xor_sync(0xffffffffu, rn, d);
                rd += __shfl_xor_sync(0xffffffffu, rd, d);
            }
            // finalize v (every lane, redundantly)
            float vv   = __uint_as_float(w8);
            float num  = fmaf(pcm, vv, pcc) + rn;
            float den  = pa + rd + EPS_;
            float vnew = num * rcpf_(den);
            // broadcast: lanes 0..7 send this group's v to all 8 ranks (skip final set)
            if (sender && (t != T_ - 1 || u != UNFOLDS - 1))
                st_cluster_f32(rbase + (uint32_t)mw * (U_ * 4), vnew);
            if (u == UNFOLDS - 1) {
                if (s == 0) out[((size_t)b * T_ + t) * U_ + jg] = fmaf(vnew, pow_, pob_);
                vlast = vnew;
            }
        }
    }
    if (s == 0) out[(size_t)B_ * T_ * U_ + b * U_ + jg] = vlast;   // h_final
    cluster_sync_();   // no CTA exits while peers may still store into its SMEM
}

// ---------------- launch ----------------
extern "C" void kernel_launch(void* const* d_in, const int* in_sizes, int n_in,
                              void* d_out, int out_size)
{
    const float* x     = (const float*)d_in[0];
    const float* h0    = (const float*)d_in[1];
    const float* gleak = (const float*)d_in[2];
    const float* vleak = (const float*)d_in[3];
    const float* cm    = (const float*)d_in[4];
    const float* sigma = (const float*)d_in[5];
    const float* mu    = (const float*)d_in[6];
    const float* w     = (const float*)d_in[7];
    const float* erev  = (const float*)d_in[8];
    const float* ssig  = (const float*)d_in[9];
    const float* smu   = (const float*)d_in[10];
    const float* sw    = (const float*)d_in[11];
    const float* serev = (const float*)d_in[12];
    const float* iw    = (const float*)d_in[13];
    const float* ib    = (const float*)d_in[14];
    const float* ow    = (const float*)d_in[15];
    const float* ob    = (const float*)d_in[16];

    ltc_prep<<<64, 256>>>(sigma, mu, w, erev, ssig, smu, sw, serev, iw, ib, gleak, vleak, cm);
    ltc_main<<<B_ * RANKS, NTH>>>(x, h0, ow, ob, (float*)d_out);
}